// round 1
// baseline (speedup 1.0000x reference)
#include <cuda_runtime.h>
#include <cuda_bf16.h>
#include <cstdint>

// Problem constants (fixed by the dataset)
#define MAXN 50000
#define IN_DIM 128
#define NUM_HEADS 8
#define HEAD_DIM 16
#define HD 128              // NUM_HEADS*HEAD_DIM
#define TILE_N 64           // nodes per block in QKV GEMM

// Scratch (static device arrays; no allocation allowed)
__device__ float g_Q[(size_t)MAXN * HD];   // pre-scaled by 0.25
__device__ float g_K[(size_t)MAXN * HD];
__device__ float g_V[(size_t)MAXN * HD];
__device__ float g_z[(size_t)MAXN * NUM_HEADS];

// ---------------------------------------------------------------------------
// Kernel 1: fused QKV projection.
// Block = 384 threads: thread group m = tid/128 handles {Q,K,V}, column j=tid%128.
// Each block processes TILE_N=64 nodes; h tile transposed into smem so the
// inner loop does broadcast LDS.128 + 4 FFMA per load.
// Q gets *0.25 folded in (score/scale in reference).
// ---------------------------------------------------------------------------
__global__ __launch_bounds__(384) void qkv_kernel(
    const float* __restrict__ h,
    const float* __restrict__ Wq, const float* __restrict__ Wk, const float* __restrict__ Wv,
    const float* __restrict__ bq, const float* __restrict__ bk, const float* __restrict__ bv,
    int N)
{
    __shared__ alignas(16) float hT[IN_DIM][TILE_N + 4];  // stride 68 (4-byte-bank step 4)

    const int n0  = blockIdx.x * TILE_N;
    const int tid = threadIdx.x;

    // Load & transpose the h tile: hT[k][n] = h[n0+n][k]
    for (int idx = tid; idx < TILE_N * IN_DIM; idx += 384) {
        int n = idx >> 7;
        int k = idx & 127;
        float val = 0.f;
        if (n0 + n < N) val = h[(size_t)(n0 + n) * IN_DIM + k];
        hT[k][n] = val;
    }
    __syncthreads();

    const int m = tid >> 7;       // 0=Q, 1=K, 2=V
    const int j = tid & 127;      // output column
    const float* W = (m == 0) ? Wq : ((m == 1) ? Wk : Wv);
    const float* b = (m == 0) ? bq : ((m == 1) ? bk : bv);
    float* outbuf  = (m == 0) ? g_Q : ((m == 1) ? g_K : g_V);
    const float mul = (m == 0) ? 0.25f : 1.0f;

    float acc[TILE_N];
#pragma unroll
    for (int n = 0; n < TILE_N; n++) acc[n] = 0.f;

    const float* Wc = W + j;      // column j, stride 128 over k
#pragma unroll 4
    for (int k = 0; k < IN_DIM; k++) {
        float w = __ldg(Wc + (size_t)k * HD);
#pragma unroll
        for (int nn = 0; nn < TILE_N; nn += 4) {
            float4 hv = *reinterpret_cast<const float4*>(&hT[k][nn]);
            acc[nn + 0] = fmaf(hv.x, w, acc[nn + 0]);
            acc[nn + 1] = fmaf(hv.y, w, acc[nn + 1]);
            acc[nn + 2] = fmaf(hv.z, w, acc[nn + 2]);
            acc[nn + 3] = fmaf(hv.w, w, acc[nn + 3]);
        }
    }

    const float bias = __ldg(b + j);
#pragma unroll
    for (int n = 0; n < TILE_N; n++) {
        if (n0 + n < N)
            outbuf[(size_t)(n0 + n) * HD + j] = (acc[n] + bias) * mul;
    }
}

// ---------------------------------------------------------------------------
// Kernel 2: per-edge score + scatter.
// One warp per edge (grid-stride). Lane l owns dims [4l,4l+4) => head h=l>>2.
// Per-head dot reduced with 2 shuffles; exp(clip) applied; V*score scattered
// with red.global.add.v4.f32 (16B vector reduction, sm_90+); z scattered
// with one scalar atomicAdd per head (lanes l%4==0).
// ---------------------------------------------------------------------------
__global__ void edge_kernel(const int* __restrict__ src, const int* __restrict__ dst,
                            float* __restrict__ out, int E)
{
    const int lane   = threadIdx.x & 31;
    const int warp   = (blockIdx.x * blockDim.x + threadIdx.x) >> 5;
    const int nwarps = (gridDim.x * blockDim.x) >> 5;

    for (int e = warp; e < E; e += nwarps) {
        const int s = __ldg(src + e);
        const int d = __ldg(dst + e);

        const float4 q = *reinterpret_cast<const float4*>(g_Q + (size_t)d * HD + lane * 4);
        const float4 k = *reinterpret_cast<const float4*>(g_K + (size_t)s * HD + lane * 4);

        float sc = q.x * k.x + q.y * k.y + q.z * k.z + q.w * k.w;
        sc += __shfl_xor_sync(0xffffffffu, sc, 1);
        sc += __shfl_xor_sync(0xffffffffu, sc, 2);   // all 4 lanes of the head group hold sc
        sc = __expf(fminf(fmaxf(sc, -5.f), 5.f));

        const float4 v = *reinterpret_cast<const float4*>(g_V + (size_t)s * HD + lane * 4);
        float* o = out + (size_t)d * HD + lane * 4;
        asm volatile("red.global.add.v4.f32 [%0], {%1,%2,%3,%4};"
                     :: "l"(o), "f"(v.x * sc), "f"(v.y * sc), "f"(v.z * sc), "f"(v.w * sc)
                     : "memory");

        if ((lane & 3) == 0)
            atomicAdd(g_z + (size_t)d * NUM_HEADS + (lane >> 2), sc);
    }
}

// ---------------------------------------------------------------------------
// Kernel 3: normalize out by z.
// ---------------------------------------------------------------------------
__global__ void div_kernel(float* __restrict__ out, int total)
{
    int i = blockIdx.x * blockDim.x + threadIdx.x;
    if (i < total) {
        int n  = i >> 7;        // node
        int hh = (i >> 4) & 7;  // head
        out[i] = out[i] / g_z[(size_t)n * NUM_HEADS + hh];
    }
}

// ---------------------------------------------------------------------------
extern "C" void kernel_launch(void* const* d_in, const int* in_sizes, int n_in,
                              void* d_out, int out_size)
{
    const float* h  = (const float*)d_in[0];
    const int* src  = (const int*)d_in[1];
    const int* dst  = (const int*)d_in[2];
    const float* Wq = (const float*)d_in[3];
    const float* Wk = (const float*)d_in[4];
    const float* Wv = (const float*)d_in[5];
    const float* bq = (const float*)d_in[6];
    const float* bk = (const float*)d_in[7];
    const float* bv = (const float*)d_in[8];
    float* out = (float*)d_out;

    const int N = in_sizes[0] / IN_DIM;
    const int E = in_sizes[1];

    // Zero accumulators (memset nodes are graph-capturable)
    cudaMemsetAsync(out, 0, (size_t)out_size * sizeof(float));
    void* zptr = nullptr;
    cudaGetSymbolAddress(&zptr, g_z);
    cudaMemsetAsync(zptr, 0, (size_t)N * NUM_HEADS * sizeof(float));

    // 1) QKV projection
    int gemm_blocks = (N + TILE_N - 1) / TILE_N;
    qkv_kernel<<<gemm_blocks, 384>>>(h, Wq, Wk, Wv, bq, bk, bv, N);

    // 2) Edge scatter
    edge_kernel<<<4096, 256>>>(src, dst, out, E);

    // 3) Normalize
    int total = N * HD;
    div_kernel<<<(total + 255) / 256, 256>>>(out, total);
}

// round 2
// speedup vs baseline: 1.3141x; 1.3141x over previous
#include <cuda_runtime.h>
#include <cuda_bf16.h>
#include <cstdint>

typedef unsigned long long ull;

// Problem constants (fixed by the dataset)
#define MAXN 50000
#define IN_DIM 128
#define NUM_HEADS 8
#define HEAD_DIM 16
#define HD 128              // NUM_HEADS*HEAD_DIM
#define TILE_N 64           // nodes per block tile in QKV GEMM

// smem layout for qkv: hT[128][68] floats, then Ws[128][128] floats
#define HT_STRIDE 68
#define SMEM_HT_FLOATS (IN_DIM * HT_STRIDE)
#define SMEM_WS_FLOATS (IN_DIM * HD)
#define QKV_SMEM_BYTES ((SMEM_HT_FLOATS + SMEM_WS_FLOATS) * 4)

// Scratch (static device arrays; no allocation allowed)
__device__ float g_Q[(size_t)MAXN * HD];   // pre-scaled by 0.25
__device__ float g_K[(size_t)MAXN * HD];
__device__ float g_V[(size_t)MAXN * HD];
__device__ float g_z[(size_t)MAXN * NUM_HEADS];

// ---------------------------------------------------------------------------
// Kernel 1: QKV projection as tiled SGEMM with packed f32x2 FMA.
// grid = (ceil(N/64), 3); blockIdx.y selects {Q,K,V}.
// Block computes a [64 nodes x 128 cols] tile. 256 threads; each thread owns
// an 8-node x 4-col micro-tile held as 16 packed f32x2 accumulators (the pair
// runs over adjacent nodes, which share the same W scalar).
// Per k: 2x LDS.v2.b64 (hT, warp-broadcast) + 1x LDS.128 (Ws) + 4 mov.b64
// (broadcast w into both halves) + 16x fma.rn.f32x2.
// ---------------------------------------------------------------------------
__global__ __launch_bounds__(256) void qkv_kernel(
    const float* __restrict__ h,
    const float* __restrict__ Wq, const float* __restrict__ Wk, const float* __restrict__ Wv,
    const float* __restrict__ bq, const float* __restrict__ bk, const float* __restrict__ bv,
    int N)
{
    extern __shared__ float smem[];
    float* hT = smem;                    // [128][68]
    float* Ws = smem + SMEM_HT_FLOATS;   // [128][128]

    const int m  = blockIdx.y;           // 0=Q, 1=K, 2=V
    const float* W = (m == 0) ? Wq : ((m == 1) ? Wk : Wv);
    const float* b = (m == 0) ? bq : ((m == 1) ? bk : bv);
    float* outbuf  = (m == 0) ? g_Q : ((m == 1) ? g_K : g_V);
    const float mul = (m == 0) ? 0.25f : 1.0f;

    const int n0  = blockIdx.x * TILE_N;
    const int tid = threadIdx.x;

    // Stage W tile (coalesced both sides): 16384 floats
    for (int i = tid * 4; i < IN_DIM * HD; i += 256 * 4) {
        *reinterpret_cast<float4*>(&Ws[i]) = *reinterpret_cast<const float4*>(&W[i]);
    }
    // Stage h tile transposed: hT[k][n] = h[n0+n][k] (zero-fill OOB nodes)
    for (int idx = tid; idx < TILE_N * IN_DIM; idx += 256) {
        int n = idx >> 7;
        int k = idx & 127;
        float v = 0.f;
        if (n0 + n < N) v = h[(size_t)(n0 + n) * IN_DIM + k];
        hT[k * HT_STRIDE + n] = v;
    }
    __syncthreads();

    const int cg = tid & 31;   // col group: cols [4*cg, 4*cg+4)
    const int ng = tid >> 5;   // node group: nodes [8*ng, 8*ng+8)

    const unsigned smem_base = (unsigned)__cvta_generic_to_shared(smem);
    const unsigned hbase = smem_base + (unsigned)(ng * 8) * 4u;                 // + k*272
    const unsigned wbase = smem_base + (unsigned)SMEM_HT_FLOATS * 4u + (unsigned)cg * 16u;  // + k*512

    ull acc[16];
#pragma unroll
    for (int i = 0; i < 16; i++) acc[i] = 0ull;   // {0.f, 0.f}

#pragma unroll 8
    for (int k = 0; k < IN_DIM; k++) {
        const unsigned ha = hbase + (unsigned)k * (HT_STRIDE * 4);
        const unsigned wa = wbase + (unsigned)k * (HD * 4);

        ull h01, h23, h45, h67;
        asm volatile("ld.shared.v2.b64 {%0,%1}, [%2];"
                     : "=l"(h01), "=l"(h23) : "r"(ha));
        asm volatile("ld.shared.v2.b64 {%0,%1}, [%2];"
                     : "=l"(h45), "=l"(h67) : "r"(ha + 16u));

        unsigned w0, w1, w2, w3;
        asm volatile("ld.shared.v4.b32 {%0,%1,%2,%3}, [%4];"
                     : "=r"(w0), "=r"(w1), "=r"(w2), "=r"(w3) : "r"(wa));

        ull wp0, wp1, wp2, wp3;
        asm("mov.b64 %0, {%1,%1};" : "=l"(wp0) : "r"(w0));
        asm("mov.b64 %0, {%1,%1};" : "=l"(wp1) : "r"(w1));
        asm("mov.b64 %0, {%1,%1};" : "=l"(wp2) : "r"(w2));
        asm("mov.b64 %0, {%1,%1};" : "=l"(wp3) : "r"(w3));

#define FMA2(a, hp, wp) asm("fma.rn.f32x2 %0, %1, %2, %0;" : "+l"(a) : "l"(hp), "l"(wp))
        FMA2(acc[ 0], h01, wp0); FMA2(acc[ 1], h01, wp1);
        FMA2(acc[ 2], h01, wp2); FMA2(acc[ 3], h01, wp3);
        FMA2(acc[ 4], h23, wp0); FMA2(acc[ 5], h23, wp1);
        FMA2(acc[ 6], h23, wp2); FMA2(acc[ 7], h23, wp3);
        FMA2(acc[ 8], h45, wp0); FMA2(acc[ 9], h45, wp1);
        FMA2(acc[10], h45, wp2); FMA2(acc[11], h45, wp3);
        FMA2(acc[12], h67, wp0); FMA2(acc[13], h67, wp1);
        FMA2(acc[14], h67, wp2); FMA2(acc[15], h67, wp3);
#undef FMA2
    }

    // Bias for this thread's 4 columns
    const int j0 = cg * 4;
    const float4 bj = *reinterpret_cast<const float4*>(&b[j0]);

    // Unpack: acc[np*4 + c] holds nodes (8*ng + 2*np, +1) for column j0+c
    float vals[8][4];
#pragma unroll
    for (int np = 0; np < 4; np++) {
#pragma unroll
        for (int c = 0; c < 4; c++) {
            unsigned lo, hi;
            asm("mov.b64 {%0,%1}, %2;" : "=r"(lo), "=r"(hi) : "l"(acc[np * 4 + c]));
            vals[2 * np + 0][c] = __uint_as_float(lo);
            vals[2 * np + 1][c] = __uint_as_float(hi);
        }
    }

#pragma unroll
    for (int r = 0; r < 8; r++) {
        int node = n0 + ng * 8 + r;
        if (node < N) {
            float4 o;
            o.x = (vals[r][0] + bj.x) * mul;
            o.y = (vals[r][1] + bj.y) * mul;
            o.z = (vals[r][2] + bj.z) * mul;
            o.w = (vals[r][3] + bj.w) * mul;
            *reinterpret_cast<float4*>(&outbuf[(size_t)node * HD + j0]) = o;
        }
    }
}

// ---------------------------------------------------------------------------
// Kernel 2: per-edge score + scatter.
// One warp per edge (grid-stride). Lane l owns dims [4l,4l+4) => head h=l>>2.
// ---------------------------------------------------------------------------
__global__ void edge_kernel(const int* __restrict__ src, const int* __restrict__ dst,
                            float* __restrict__ out, int E)
{
    const int lane   = threadIdx.x & 31;
    const int warp   = (blockIdx.x * blockDim.x + threadIdx.x) >> 5;
    const int nwarps = (gridDim.x * blockDim.x) >> 5;

    for (int e = warp; e < E; e += nwarps) {
        const int s = __ldg(src + e);
        const int d = __ldg(dst + e);

        const float4 q = *reinterpret_cast<const float4*>(g_Q + (size_t)d * HD + lane * 4);
        const float4 k = *reinterpret_cast<const float4*>(g_K + (size_t)s * HD + lane * 4);

        float sc = q.x * k.x + q.y * k.y + q.z * k.z + q.w * k.w;
        sc += __shfl_xor_sync(0xffffffffu, sc, 1);
        sc += __shfl_xor_sync(0xffffffffu, sc, 2);   // all 4 lanes of the head group hold sc
        sc = __expf(fminf(fmaxf(sc, -5.f), 5.f));

        const float4 v = *reinterpret_cast<const float4*>(g_V + (size_t)s * HD + lane * 4);
        float* o = out + (size_t)d * HD + lane * 4;
        asm volatile("red.global.add.v4.f32 [%0], {%1,%2,%3,%4};"
                     :: "l"(o), "f"(v.x * sc), "f"(v.y * sc), "f"(v.z * sc), "f"(v.w * sc)
                     : "memory");

        if ((lane & 3) == 0)
            atomicAdd(g_z + (size_t)d * NUM_HEADS + (lane >> 2), sc);
    }
}

// ---------------------------------------------------------------------------
// Kernel 3: normalize out by z.
// ---------------------------------------------------------------------------
__global__ void div_kernel(float* __restrict__ out, int total)
{
    int i = blockIdx.x * blockDim.x + threadIdx.x;
    if (i < total) {
        int n  = i >> 7;        // node
        int hh = (i >> 4) & 7;  // head
        out[i] = out[i] / g_z[(size_t)n * NUM_HEADS + hh];
    }
}

// ---------------------------------------------------------------------------
extern "C" void kernel_launch(void* const* d_in, const int* in_sizes, int n_in,
                              void* d_out, int out_size)
{
    const float* h  = (const float*)d_in[0];
    const int* src  = (const int*)d_in[1];
    const int* dst  = (const int*)d_in[2];
    const float* Wq = (const float*)d_in[3];
    const float* Wk = (const float*)d_in[4];
    const float* Wv = (const float*)d_in[5];
    const float* bq = (const float*)d_in[6];
    const float* bk = (const float*)d_in[7];
    const float* bv = (const float*)d_in[8];
    float* out = (float*)d_out;

    const int N = in_sizes[0] / IN_DIM;
    const int E = in_sizes[1];

    // Zero accumulators (memset nodes are graph-capturable)
    cudaMemsetAsync(out, 0, (size_t)out_size * sizeof(float));
    void* zptr = nullptr;
    cudaGetSymbolAddress(&zptr, g_z);
    cudaMemsetAsync(zptr, 0, (size_t)N * NUM_HEADS * sizeof(float));

    // 1) QKV projection (dynamic smem > 48KB needs the attribute)
    static bool attr_set = false;
    if (!attr_set) {
        cudaFuncSetAttribute(qkv_kernel, cudaFuncAttributeMaxDynamicSharedMemorySize,
                             QKV_SMEM_BYTES);
        attr_set = true;
    }
    dim3 gemm_grid((N + TILE_N - 1) / TILE_N, 3);
    qkv_kernel<<<gemm_grid, 256, QKV_SMEM_BYTES>>>(h, Wq, Wk, Wv, bq, bk, bv, N);

    // 2) Edge scatter
    edge_kernel<<<4096, 256>>>(src, dst, out, E);

    // 3) Normalize
    int total = N * HD;
    div_kernel<<<(total + 255) / 256, 256>>>(out, total);
}